// round 7
// baseline (speedup 1.0000x reference)
#include <cuda_runtime.h>

// KVCacheHeadAttention: B=32, E=4096 -> D=128, MAX_TOKENS=2048.
// Prefix-softmax: out[b,s,:] = sum_{t<=s} e_t*v[b,t,:] / sum_{t<=s} e_t.
// R6: TWO kernels.
//  K1 qkv_part: 96 CTAs, split-K partials, no atomics (kernel boundary = sync).
//  K2 fused:    score + chunk totals + decoupled lookback + scan.
//     Publication via st.release.gpu / ld.acquire.gpu (NO __threadfence ->
//     no CCTL.IVALL L1 flush), lane-0-only spin. Per-b done counter resets
//     flags so graph replays start clean.

#define BB 32
#define DD 128
#define D4 32
#define EE 4096
#define MAXT 2048
#define CHUNK 128
#define MAXCH 16
#define NSPLIT 8
#define ECH 128

__device__ float g_part[3][NSPLIT][BB][DD];  // qkv split-K partials
__device__ float g_ctot[BB][MAXCH][DD];      // chunk numerator totals
__device__ float g_dtot[BB][MAXCH];          // chunk denominator totals
__device__ int   g_flag[BB][MAXCH];          // publish flags (zero-init)
__device__ int   g_doneb[BB];                // per-b finished counters

__device__ __forceinline__ float4 f4add(float4 a, float4 b) {
    return make_float4(a.x+b.x, a.y+b.y, a.z+b.z, a.w+b.w);
}
__device__ __forceinline__ float4 f4fma(float s, float4 v, float4 a) {
    return make_float4(fmaf(s,v.x,a.x), fmaf(s,v.y,a.y),
                       fmaf(s,v.z,a.z), fmaf(s,v.w,a.w));
}
__device__ __forceinline__ float4 f4scale(float4 v, float s) {
    return make_float4(v.x*s, v.y*s, v.z*s, v.w*s);
}
__device__ __forceinline__ void st_release_gpu(int* p, int v) {
    asm volatile("st.release.gpu.global.b32 [%0], %1;" :: "l"(p), "r"(v) : "memory");
}
__device__ __forceinline__ int ld_acquire_gpu(const int* p) {
    int v;
    asm volatile("ld.acquire.gpu.global.b32 %0, [%1];" : "=r"(v) : "l"(p) : "memory");
    return v;
}

// ---------------- K1: QKV split-K partials (96 blocks, 512 thr) ----------
// block = (m, dtile, esplit): 32x32 output tile, 512-wide E slice,
// double-buffered smem, partials to g_part (no atomics).
__global__ __launch_bounds__(512) void qkv_part_kernel(
    const float* __restrict__ x,  const float* __restrict__ Wq,
    const float* __restrict__ Wk, const float* __restrict__ Wv) {
    __shared__ float xs[2][32][ECH + 4];
    __shared__ float ws[2][32][ECH + 4];

    int lin = blockIdx.x;
    int m   = lin >> 5;
    int r   = lin & 31;
    int dt  = r >> 3;
    int esp = r & 7;
    const float* W = (m == 0) ? Wq : ((m == 1) ? Wk : Wv);

    int tid = threadIdx.x;
    int ti  = tid & 31;          // batch row
    int tj  = tid >> 5;          // 0..15 -> d pair {tj, tj+16}
    float a0 = 0.f, a1 = 0.f;

    // preload chunk 0
    {
        int e0 = esp * 512;
        for (int i = tid; i < 32 * (ECH / 4); i += 512) {
            int rr = i >> 5;
            int j  = (i & 31) << 2;
            *(float4*)&xs[0][rr][j] = *(const float4*)(x + (size_t)rr * EE + e0 + j);
            *(float4*)&ws[0][rr][j] = *(const float4*)(W + (size_t)(dt * 32 + rr) * EE + e0 + j);
        }
    }
    __syncthreads();

    for (int ch = 0; ch < 4; ch++) {
        int cur = ch & 1, nxt = cur ^ 1;
        if (ch < 3) {
            int e0 = esp * 512 + (ch + 1) * ECH;
            for (int i = tid; i < 32 * (ECH / 4); i += 512) {
                int rr = i >> 5;
                int j  = (i & 31) << 2;
                *(float4*)&xs[nxt][rr][j] = *(const float4*)(x + (size_t)rr * EE + e0 + j);
                *(float4*)&ws[nxt][rr][j] = *(const float4*)(W + (size_t)(dt * 32 + rr) * EE + e0 + j);
            }
        }
        #pragma unroll
        for (int e = 0; e < ECH; e += 4) {
            float4 xa = *(float4*)&xs[cur][ti][e];
            float4 wa = *(float4*)&ws[cur][tj][e];
            float4 wb = *(float4*)&ws[cur][tj + 16][e];
            a0 += xa.x*wa.x + xa.y*wa.y + xa.z*wa.z + xa.w*wa.w;
            a1 += xa.x*wb.x + xa.y*wb.y + xa.z*wb.z + xa.w*wb.w;
        }
        __syncthreads();
    }
    g_part[m][esp][ti][dt * 32 + tj]      = a0;
    g_part[m][esp][ti][dt * 32 + tj + 16] = a1;
}

// -------- K2: fused score + chunk totals + lookback + scan ---------------
__global__ __launch_bounds__(512, 3) void fused_kernel(
    const float* __restrict__ kv, const int* __restrict__ np,
    float* __restrict__ out, int max_k) {

    __shared__ float  qs[DD], kn[DD], es[CHUNK], rden[CHUNK];
    __shared__ float4 vns4[D4];
    __shared__ float4 part[16][D4];
    __shared__ float  pden[16];
    __shared__ float  warp_sums[4];
    __shared__ int    last;

    int tid = threadIdx.x;
    int b   = blockIdx.y, c = blockIdx.x;

    // prologue: reduce split-K partials (96 threads, float4)
    if (tid < 96) {
        int m  = tid >> 5;
        int dd = tid & 31;
        float4 acc = make_float4(0.f, 0.f, 0.f, 0.f);
        #pragma unroll
        for (int e = 0; e < NSPLIT; e++)
            acc = f4add(acc, *((const float4*)&g_part[m][e][b][0] + dd));
        if (m == 0)      *((float4*)qs + dd) = acc;
        else if (m == 1) *((float4*)kn + dd) = acc;
        else             vns4[dd] = acc;
    }
    __syncthreads();

    int npos = np[b];
    int t0   = c * CHUNK;

    // phase C: scores (4 lanes per token, quarter-dot + shfl)
    {
        int tok = tid >> 2, qq = tid & 3;
        int t   = t0 + tok;
        const float* krow = (t == npos) ? kn
                          : kv + ((size_t)b * MAXT + t) * DD;
        float sdot = 0.0f;
        int d0 = qq * 32;
        #pragma unroll
        for (int d = 0; d < 32; d += 4) {
            float4 kk = *(const float4*)(krow + d0 + d);
            sdot += qs[d0+d]*kk.x + qs[d0+d+1]*kk.y
                  + qs[d0+d+2]*kk.z + qs[d0+d+3]*kk.w;
        }
        sdot += __shfl_xor_sync(0xffffffffu, sdot, 1);
        sdot += __shfl_xor_sync(0xffffffffu, sdot, 2);
        float e = (t < max_k) ? expf(sdot * 0.08838834764831845f) : 0.0f;
        if (qq == 0) es[tok] = e;
    }
    __syncthreads();

    // phase D: 8-token numerator partials + den warp-scan
    int s  = tid >> 5;       // warp = 8-token sub-chunk
    int d4 = tid & 31;
    int tb = t0 + s * 8;
    const float4* vbase = (const float4*)(kv + (size_t)BB * MAXT * DD
                                          + ((size_t)b * MAXT + tb) * DD) + d4;
    {
        float4 psum = make_float4(0.f, 0.f, 0.f, 0.f);
        #pragma unroll
        for (int uu = 0; uu < 8; uu++) {
            float4 xv = vbase[(size_t)uu * D4];
            if (tb + uu == npos) xv = vns4[d4];
            psum = f4fma(es[s * 8 + uu], xv, psum);
        }
        part[s][d4] = psum;
    }
    float dv = 0.0f;
    if (tid < 128) {
        dv = es[tid];
        int lane = tid & 31;
        #pragma unroll
        for (int o = 1; o < 32; o <<= 1) {
            float n = __shfl_up_sync(0xffffffffu, dv, o);
            if (lane >= o) dv += n;
        }
        if (lane == 31) warp_sums[tid >> 5] = dv;
    }
    __syncthreads();

    // own exclusive prefix (registers) + publish chunk totals
    float4 pref = make_float4(0.f, 0.f, 0.f, 0.f);
    for (int j = 0; j < s; j++) pref = f4add(pref, part[j][d4]);
    if (s == 15)
        *((float4*)&g_ctot[b][c][0] + d4) = f4add(pref, part[15][d4]);
    if (tid == 0)
        g_dtot[b][c] = warp_sums[0] + warp_sums[1] + warp_sums[2] + warp_sums[3];
    __syncthreads();
    if (tid == 0) st_release_gpu(&g_flag[b][c], 1);

    // phase E: lookback — warp i fetches predecessor i (lane-0 spin)
    if (s < c) {
        if (d4 == 0) {
            while (ld_acquire_gpu(&g_flag[b][s]) == 0) { __nanosleep(64); }
        }
        __syncwarp();
        part[s][d4] = *((const float4*)&g_ctot[b][s][0] + d4);
        if (d4 == 0) pden[s] = g_dtot[b][s];
    } else {
        part[s][d4] = make_float4(0.f, 0.f, 0.f, 0.f);
        if (d4 == 0) pden[s] = 0.0f;
    }
    __syncthreads();

    // bases + reciprocal denominators
    float4 bnum = make_float4(0.f, 0.f, 0.f, 0.f);
    float  bden = 0.0f;
    for (int i = 0; i < c; i++) {
        bnum = f4add(bnum, part[i][d4]);
        bden += pden[i];
    }
    if (tid < 128) {
        int w = tid >> 5;
        float wb = bden;
        for (int i = 0; i < w; i++) wb += warp_sums[i];
        rden[tid] = 1.0f / (wb + dv);
    }
    __syncthreads();

    // phase F: final scan (V reload is L1/L2-hot), scaled stores
    float4 acc = f4add(bnum, pref);
    float4* obase = (float4*)(out + ((size_t)b * max_k + tb) * DD) + d4;
    #pragma unroll
    for (int uu = 0; uu < 8; uu++) {
        float4 xv = vbase[(size_t)uu * D4];
        if (tb + uu == npos) xv = vns4[d4];
        acc = f4fma(es[s * 8 + uu], xv, acc);
        if (tb + uu < max_k)
            obase[(size_t)uu * D4] = f4scale(acc, rden[s * 8 + uu]);
    }

    // phase G: per-b self-clean for graph replay
    __syncthreads();                         // all flag reads & outputs done
    if (tid == 0)
        last = (atomicAdd(&g_doneb[b], 1) == (int)gridDim.x - 1);
    __syncthreads();
    if (last) {
        if (tid < MAXCH) g_flag[b][tid] = 0;
        if (tid == 0)    g_doneb[b] = 0;
    }
}

// ----------------------------------------------------------------- launch
extern "C" void kernel_launch(void* const* d_in, const int* in_sizes, int n_in,
                              void* d_out, int out_size) {
    const float* x   = (const float*)d_in[0];
    const float* Wq  = (const float*)d_in[1];
    const float* Wk  = (const float*)d_in[2];
    const float* Wv  = (const float*)d_in[3];
    const float* kvc = (const float*)d_in[4];
    const int*   np  = (const int*)d_in[5];
    float* out = (float*)d_out;

    int max_k   = out_size / (BB * DD);
    int nchunks = (max_k + CHUNK - 1) / CHUNK;   // 12 for max_k=1536

    qkv_part_kernel<<<96, 512>>>(x, Wq, Wk, Wv);
    fused_kernel<<<dim3(nchunks, BB), 512>>>(kvc, np, out, max_k);
}